// round 11
// baseline (speedup 1.0000x reference)
#include <cuda_runtime.h>
#include <cstdint>

#define NN 100000
#define D 128
#define NTILES 782          // ceil(100000/128)

// ---------------- scratch (no allocations allowed) ----------------
__device__ float g_A[(size_t)NN * D];   // agg / gcn-accumulator
__device__ float g_H[(size_t)NN * D];   // h = x @ W_gcn / agg2
__device__ float g_X[(size_t)NN * D];   // x after down-stage / x2 after gcn
__device__ float g_cnt[NN];             // counts / degrees

// ================= PTX helpers =================
__device__ __forceinline__ uint32_t smem_u32(const void* p) {
    uint32_t a;
    asm("{ .reg .u64 t; cvta.to.shared.u64 t, %1; cvt.u32.u64 %0, t; }" : "=r"(a) : "l"(p));
    return a;
}
#define CP_ASYNC16(dst, src) \
    asm volatile("cp.async.cg.shared.global [%0], [%1], 16;" :: "r"(dst), "l"(src) : "memory")
#define CP_COMMIT() asm volatile("cp.async.commit_group;" ::: "memory")
#define CP_WAIT(n)  asm volatile("cp.async.wait_group %0;" :: "n"(n) : "memory")

// ---------------- scatter-mean accumulate: warp per edge (proven R5 path) ----------------
__global__ void scatter_accum_kernel(const float* __restrict__ feat,
                                     const int* __restrict__ src,
                                     const int* __restrict__ dst,
                                     float* __restrict__ agg,
                                     float* __restrict__ cnt,
                                     int nE) {
    int gtid = blockIdx.x * blockDim.x + threadIdx.x;
    int e = gtid >> 5;
    int lane = gtid & 31;
    if (e >= nE) return;
    int s = src[e];
    int d = dst[e];
    float4 v = ((const float4*)(feat + (size_t)s * D))[lane];
    float* p = agg + (size_t)d * D + lane * 4;
    atomicAdd(p + 0, v.x);
    atomicAdd(p + 1, v.y);
    atomicAdd(p + 2, v.z);
    atomicAdd(p + 3, v.w);
    if (lane == 0) atomicAdd(cnt + d, 1.0f);
}

// ---------------- in-degree counting ----------------
__global__ void degree_kernel(const int* __restrict__ dst,
                              float* __restrict__ cnt, int nE) {
    int e = blockIdx.x * blockDim.x + threadIdx.x;
    if (e < nE) atomicAdd(cnt + dst[e], 1.0f);
}

// ---------------- GCN normalized scatter: warp per edge ----------------
__global__ void gcn_scatter_kernel(const float* __restrict__ h,
                                   const int* __restrict__ src,
                                   const int* __restrict__ dst,
                                   const float* __restrict__ cnt,
                                   float* __restrict__ acc,
                                   int nE) {
    int gtid = blockIdx.x * blockDim.x + threadIdx.x;
    int e = gtid >> 5;
    int lane = gtid & 31;
    if (e >= nE) return;
    int s = src[e];
    int d = dst[e];
    float norm = rsqrtf((cnt[s] + 1.0f) * (cnt[d] + 1.0f));
    float4 v = ((const float4*)(h + (size_t)s * D))[lane];
    float* p = acc + (size_t)d * D + lane * 4;
    atomicAdd(p + 0, v.x * norm);
    atomicAdd(p + 1, v.y * norm);
    atomicAdd(p + 2, v.z * norm);
    atomicAdd(p + 3, v.w * norm);
}

// ---------------- GCN epilogue: x2 = acc + h/deg + b ----------------
__global__ void gcn_finish_kernel(const float* __restrict__ acc,
                                  const float* __restrict__ h,
                                  const float* __restrict__ cnt,
                                  const float* __restrict__ bias,
                                  float* __restrict__ out) {
    int i = blockIdx.x * blockDim.x + threadIdx.x;   // float4 index
    if (i >= NN * (D / 4)) return;
    int row = i >> 5;
    int c4 = i & 31;
    float inv = 1.0f / (cnt[row] + 1.0f);
    float4 a = ((const float4*)acc)[i];
    float4 hh = ((const float4*)h)[i];
    float4 b = ((const float4*)bias)[c4];
    float4 o;
    o.x = a.x + hh.x * inv + b.x;
    o.y = a.y + hh.y * inv + b.y;
    o.z = a.z + hh.z * inv + b.z;
    o.w = a.w + hh.w * inv + b.w;
    ((float4*)out)[i] = o;
}

// ================= persistent FFMA GEMM =================
// out = f( resid + (A @ W) * scale_row + bias ),  scale_row = 1/max(cnt,1) if MEAN
// W: [K=128][N=128] row-major (as given).  A: [n][128] row-major.
// grid = 148 persistent CTAs, 256 threads, 8x8 micro-tile, BM=128, BN=128.
// smem: sW 64KB + double-buffered sA 2x64KB = 192KB.
#define FMA8(ak, wj0, wj1)                              \
    acc[i][0] = fmaf(ak, (wj0).x, acc[i][0]);           \
    acc[i][1] = fmaf(ak, (wj0).y, acc[i][1]);           \
    acc[i][2] = fmaf(ak, (wj0).z, acc[i][2]);           \
    acc[i][3] = fmaf(ak, (wj0).w, acc[i][3]);           \
    acc[i][4] = fmaf(ak, (wj1).x, acc[i][4]);           \
    acc[i][5] = fmaf(ak, (wj1).y, acc[i][5]);           \
    acc[i][6] = fmaf(ak, (wj1).z, acc[i][6]);           \
    acc[i][7] = fmaf(ak, (wj1).w, acc[i][7]);

template <bool MEAN, bool EPI>
__global__ void __launch_bounds__(256, 1)
gemm_pers_kernel(const float* __restrict__ A, const float* __restrict__ cnt,
                 const float* __restrict__ W, const float* __restrict__ bias,
                 const float* __restrict__ resid, float* __restrict__ out, int n) {
    extern __shared__ float smem[];
    float* sW = smem;                 // [128][128]
    float* sA = smem + 16384;         // [2][128][128]
    uint32_t sA_u32 = smem_u32(sA);

    int tid = threadIdx.x;
    int tx = tid & 15;                // col block: cols tx*8 .. tx*8+7
    int ty = tid >> 4;                // row block: rows ty*8 .. ty*8+7

    // ---- load W once (coalesced, 4096 float4) ----
#pragma unroll
    for (int v = 0; v < 16; ++v) {
        int idx = v * 256 + tid;
        ((float4*)sW)[idx] = ((const float4*)W)[idx];
    }

    // ---- prefetch first tile into buf 0 (full 128x128 tile = 4096 float4) ----
    {
        int row0 = blockIdx.x * 128;
#pragma unroll
        for (int v = 0; v < 16; ++v) {
            int idx = v * 256 + tid;          // 4096 float4
            int r = idx >> 5, c4 = idx & 31;
            int grow = row0 + r;
            if (grow >= n) grow = n - 1;      // clamp: junk rows discarded at store
            const float* src = A + (size_t)grow * D + c4 * 4;
            CP_ASYNC16(sA_u32 + (uint32_t)(r * 128 + c4 * 4) * 4u, src);
        }
        CP_COMMIT();
    }
    __syncthreads();   // sW visible

    int buf = 0;
    for (int t = blockIdx.x; t < NTILES; t += gridDim.x, buf ^= 1) {
        int tn = t + gridDim.x;
        if (tn < NTILES) {
            // prefetch next tile into other buffer (full 4096 float4)
            int row0n = tn * 128;
            uint32_t base = sA_u32 + (uint32_t)((buf ^ 1) * 16384) * 4u;
#pragma unroll
            for (int v = 0; v < 16; ++v) {
                int idx = v * 256 + tid;
                int r = idx >> 5, c4 = idx & 31;
                int grow = row0n + r;
                if (grow >= n) grow = n - 1;
                const float* src = A + (size_t)grow * D + c4 * 4;
                CP_ASYNC16(base + (uint32_t)(r * 128 + c4 * 4) * 4u, src);
            }
            CP_COMMIT();
            CP_WAIT(1);    // current tile's group complete; next still in flight
        } else {
            CP_WAIT(0);
        }
        __syncthreads();

        const float* sAb = sA + buf * 16384;
        float acc[8][8];
#pragma unroll
        for (int i = 0; i < 8; ++i)
#pragma unroll
            for (int j = 0; j < 8; ++j) acc[i][j] = 0.0f;

#pragma unroll 2
        for (int kb = 0; kb < 128; kb += 4) {
            float4 w0a = *(const float4*)&sW[(kb + 0) * 128 + tx * 8];
            float4 w0b = *(const float4*)&sW[(kb + 0) * 128 + tx * 8 + 4];
            float4 w1a = *(const float4*)&sW[(kb + 1) * 128 + tx * 8];
            float4 w1b = *(const float4*)&sW[(kb + 1) * 128 + tx * 8 + 4];
            float4 w2a = *(const float4*)&sW[(kb + 2) * 128 + tx * 8];
            float4 w2b = *(const float4*)&sW[(kb + 2) * 128 + tx * 8 + 4];
            float4 w3a = *(const float4*)&sW[(kb + 3) * 128 + tx * 8];
            float4 w3b = *(const float4*)&sW[(kb + 3) * 128 + tx * 8 + 4];
#pragma unroll
            for (int i = 0; i < 8; ++i) {
                float4 a = *(const float4*)&sAb[(ty * 8 + i) * 128 + kb];
                FMA8(a.x, w0a, w0b)
                FMA8(a.y, w1a, w1b)
                FMA8(a.z, w2a, w2b)
                FMA8(a.w, w3a, w3b)
            }
        }
        __syncthreads();   // buf fully consumed before next iter overwrites it

        // ---- epilogue: optional row-scale (mean), residual+bias+relu, store ----
        int row0 = t * 128;
#pragma unroll
        for (int i = 0; i < 8; ++i) {
            int grow = row0 + ty * 8 + i;
            if (grow >= n) continue;
            float sc = 1.0f;
            if (MEAN) sc = 1.0f / fmaxf(cnt[grow], 1.0f);
            float4 o0, o1;
            o0.x = acc[i][0] * sc; o0.y = acc[i][1] * sc;
            o0.z = acc[i][2] * sc; o0.w = acc[i][3] * sc;
            o1.x = acc[i][4] * sc; o1.y = acc[i][5] * sc;
            o1.z = acc[i][6] * sc; o1.w = acc[i][7] * sc;
            if (EPI) {
                const float4* rr = (const float4*)(resid + (size_t)grow * D);
                float4 r0 = rr[tx * 2], r1 = rr[tx * 2 + 1];
                float4 b0 = ((const float4*)bias)[tx * 2];
                float4 b1 = ((const float4*)bias)[tx * 2 + 1];
                o0.x = fmaxf(o0.x + r0.x + b0.x, 0.0f);
                o0.y = fmaxf(o0.y + r0.y + b0.y, 0.0f);
                o0.z = fmaxf(o0.z + r0.z + b0.z, 0.0f);
                o0.w = fmaxf(o0.w + r0.w + b0.w, 0.0f);
                o1.x = fmaxf(o1.x + r1.x + b1.x, 0.0f);
                o1.y = fmaxf(o1.y + r1.y + b1.y, 0.0f);
                o1.z = fmaxf(o1.z + r1.z + b1.z, 0.0f);
                o1.w = fmaxf(o1.w + r1.w + b1.w, 0.0f);
            }
            float4* po = (float4*)(out + (size_t)grow * D);
            po[tx * 2] = o0;
            po[tx * 2 + 1] = o1;
        }
    }
}

// ---------------- launch ----------------
extern "C" void kernel_launch(void* const* d_in, const int* in_sizes, int n_in,
                              void* d_out, int out_size) {
    const float* emb = (const float*)d_in[0];
    const float* Wd  = (const float*)d_in[1];
    const float* bd  = (const float*)d_in[2];
    const float* Wg  = (const float*)d_in[3];
    const float* bg  = (const float*)d_in[4];
    const float* Wu  = (const float*)d_in[5];
    const float* bu  = (const float*)d_in[6];
    const int* d2u = (const int*)d_in[7];
    const int* sl  = (const int*)d_in[8];
    const int* u2d = (const int*)d_in[9];
    int nE1 = in_sizes[7] / 2;   // 100000
    int nE2 = in_sizes[8] / 2;   // 600000
    int nE3 = in_sizes[9] / 2;   // 100000
    float* out = (float*)d_out;

    float *A, *H, *X, *C;
    cudaGetSymbolAddress((void**)&A, g_A);
    cudaGetSymbolAddress((void**)&H, g_H);
    cudaGetSymbolAddress((void**)&X, g_X);
    cudaGetSymbolAddress((void**)&C, g_cnt);

    const size_t featBytes = (size_t)NN * D * sizeof(float);
    const int smemBytes = (16384 + 2 * 16384) * sizeof(float);   // 192 KB
    cudaFuncSetAttribute(gemm_pers_kernel<true, true>,
                         cudaFuncAttributeMaxDynamicSharedMemorySize, smemBytes);
    cudaFuncSetAttribute(gemm_pers_kernel<false, false>,
                         cudaFuncAttributeMaxDynamicSharedMemorySize, smemBytes);

    const int gemmGrid = 148;

    // ---- stage 1: down2up mean aggregate + transform + residual relu ----
    cudaMemsetAsync(A, 0, featBytes, 0);
    cudaMemsetAsync(C, 0, NN * sizeof(float), 0);
    scatter_accum_kernel<<<(nE1 + 7) / 8, 256>>>(emb, d2u, d2u + nE1, A, C, nE1);
    gemm_pers_kernel<true, true><<<gemmGrid, 256, smemBytes>>>(A, C, Wd, bd, emb, X, NN);

    // ---- stage 2: GCN ----
    cudaMemsetAsync(C, 0, NN * sizeof(float), 0);
    degree_kernel<<<(nE2 + 255) / 256, 256>>>(sl + nE2, C, nE2);
    gemm_pers_kernel<false, false><<<gemmGrid, 256, smemBytes>>>(X, nullptr, Wg, nullptr,
                                                                 nullptr, H, NN);
    cudaMemsetAsync(A, 0, featBytes, 0);
    gcn_scatter_kernel<<<(nE2 + 7) / 8, 256>>>(H, sl, sl + nE2, C, A, nE2);
    gcn_finish_kernel<<<(NN * (D / 4) + 255) / 256, 256>>>(A, H, C, bg, X);

    // ---- stage 3: up2down mean aggregate + transform + residual relu ----
    cudaMemsetAsync(H, 0, featBytes, 0);
    cudaMemsetAsync(C, 0, NN * sizeof(float), 0);
    scatter_accum_kernel<<<(nE3 + 7) / 8, 256>>>(X, u2d, u2d + nE3, H, C, nE3);
    gemm_pers_kernel<true, true><<<gemmGrid, 256, smemBytes>>>(H, C, Wu, bu, X, out, NN);
}

// round 12
// speedup vs baseline: 1.0761x; 1.0761x over previous
#include <cuda_runtime.h>
#include <cstdint>

#define NN 100000
#define D 128

// ---------------- scratch (no allocations allowed) ----------------
__device__ float g_A[(size_t)NN * D];   // agg / gcn-accumulator
__device__ float g_H[(size_t)NN * D];   // h = x @ W_gcn / agg2
__device__ float g_X[(size_t)NN * D];   // x after down-stage / x2 after gcn
__device__ float g_cnt[NN];             // counts / degrees

// ================= PTX helpers =================
__device__ __forceinline__ uint32_t smem_u32(const void* p) {
    uint32_t a;
    asm("{ .reg .u64 t; cvta.to.shared.u64 t, %1; cvt.u32.u64 %0, t; }" : "=r"(a) : "l"(p));
    return a;
}
#define CP_ASYNC16(dst, src) \
    asm volatile("cp.async.cg.shared.global [%0], [%1], 16;" :: "r"(dst), "l"(src) : "memory")
#define CP_COMMIT() asm volatile("cp.async.commit_group;" ::: "memory")
#define CP_WAIT(n)  asm volatile("cp.async.wait_group %0;" :: "n"(n) : "memory")

// ---------------- scatter-mean accumulate: warp per edge (proven path) ----------------
__global__ void scatter_accum_kernel(const float* __restrict__ feat,
                                     const int* __restrict__ src,
                                     const int* __restrict__ dst,
                                     float* __restrict__ agg,
                                     float* __restrict__ cnt,
                                     int nE) {
    int gtid = blockIdx.x * blockDim.x + threadIdx.x;
    int e = gtid >> 5;
    int lane = gtid & 31;
    if (e >= nE) return;
    int s = src[e];
    int d = dst[e];
    float4 v = ((const float4*)(feat + (size_t)s * D))[lane];
    float* p = agg + (size_t)d * D + lane * 4;
    atomicAdd(p + 0, v.x);
    atomicAdd(p + 1, v.y);
    atomicAdd(p + 2, v.z);
    atomicAdd(p + 3, v.w);
    if (lane == 0) atomicAdd(cnt + d, 1.0f);
}

// ---------------- in-degree counting ----------------
__global__ void degree_kernel(const int* __restrict__ dst,
                              float* __restrict__ cnt, int nE) {
    int e = blockIdx.x * blockDim.x + threadIdx.x;
    if (e < nE) atomicAdd(cnt + dst[e], 1.0f);
}

// ---------------- GCN normalized scatter: warp per edge ----------------
__global__ void gcn_scatter_kernel(const float* __restrict__ h,
                                   const int* __restrict__ src,
                                   const int* __restrict__ dst,
                                   const float* __restrict__ cnt,
                                   float* __restrict__ acc,
                                   int nE) {
    int gtid = blockIdx.x * blockDim.x + threadIdx.x;
    int e = gtid >> 5;
    int lane = gtid & 31;
    if (e >= nE) return;
    int s = src[e];
    int d = dst[e];
    float norm = rsqrtf((cnt[s] + 1.0f) * (cnt[d] + 1.0f));
    float4 v = ((const float4*)(h + (size_t)s * D))[lane];
    float* p = acc + (size_t)d * D + lane * 4;
    atomicAdd(p + 0, v.x * norm);
    atomicAdd(p + 1, v.y * norm);
    atomicAdd(p + 2, v.z * norm);
    atomicAdd(p + 3, v.w * norm);
}

// ---------------- GCN epilogue: x2 = acc + h/deg + b ----------------
__global__ void gcn_finish_kernel(const float* __restrict__ acc,
                                  const float* __restrict__ h,
                                  const float* __restrict__ cnt,
                                  const float* __restrict__ bias,
                                  float* __restrict__ out) {
    int i = blockIdx.x * blockDim.x + threadIdx.x;   // float4 index
    if (i >= NN * (D / 4)) return;
    int row = i >> 5;
    int c4 = i & 31;
    float inv = 1.0f / (cnt[row] + 1.0f);
    float4 a = ((const float4*)acc)[i];
    float4 hh = ((const float4*)h)[i];
    float4 b = ((const float4*)bias)[c4];
    float4 o;
    o.x = a.x + hh.x * inv + b.x;
    o.y = a.y + hh.y * inv + b.y;
    o.z = a.z + hh.z * inv + b.z;
    o.w = a.w + hh.w * inv + b.w;
    ((float4*)out)[i] = o;
}

// ================= GEMM: BM=128, BN=128, 8x8 micro-tile, W k-slice streamed =================
// out = f( resid + (A @ W) * scale_row + bias ),  scale_row = 1/max(cnt,1) if MEAN
// smem: sA [128][128] 64KB + sW [2][32][128] 32KB = 96KB -> 2 CTAs/SM.
#define FMA8(ak, wj0, wj1)                              \
    acc[i][0] = fmaf(ak, (wj0).x, acc[i][0]);           \
    acc[i][1] = fmaf(ak, (wj0).y, acc[i][1]);           \
    acc[i][2] = fmaf(ak, (wj0).z, acc[i][2]);           \
    acc[i][3] = fmaf(ak, (wj0).w, acc[i][3]);           \
    acc[i][4] = fmaf(ak, (wj1).x, acc[i][4]);           \
    acc[i][5] = fmaf(ak, (wj1).y, acc[i][5]);           \
    acc[i][6] = fmaf(ak, (wj1).z, acc[i][6]);           \
    acc[i][7] = fmaf(ak, (wj1).w, acc[i][7]);

template <bool MEAN, bool EPI>
__global__ void __launch_bounds__(256, 2)
gemm_kernel(const float* __restrict__ A, const float* __restrict__ cnt,
            const float* __restrict__ W, const float* __restrict__ bias,
            const float* __restrict__ resid, float* __restrict__ out, int n) {
    extern __shared__ float smem[];
    float* sA = smem;                 // [128][128]
    float* sW = smem + 16384;         // [2][32][128]
    uint32_t sA_u = smem_u32(sA);
    uint32_t sW_u = smem_u32(sW);

    int tid = threadIdx.x;
    int tx = tid & 15;                // col block: cols tx*8 .. tx*8+7
    int ty = tid >> 4;                // row block: rows ty*8 .. ty*8+7
    int row0 = blockIdx.x * 128;

    // ---- A tile: 4096 float4 via cp.async (16 per thread) ----
#pragma unroll
    for (int v = 0; v < 16; ++v) {
        int idx = v * 256 + tid;
        int r = idx >> 5, c4 = idx & 31;
        int grow = row0 + r;
        if (grow >= n) grow = n - 1;      // clamp: junk rows discarded at store
        CP_ASYNC16(sA_u + (uint32_t)idx * 16u, A + (size_t)grow * D + c4 * 4);
    }
    // ---- W slice 0: [32][128] = 1024 float4 (4 per thread) ----
#pragma unroll
    for (int v = 0; v < 4; ++v) {
        int idx = v * 256 + tid;
        CP_ASYNC16(sW_u + (uint32_t)idx * 16u, W + idx * 4);
    }
    CP_COMMIT();    // group: A + W0

    float acc[8][8];
#pragma unroll
    for (int i = 0; i < 8; ++i)
#pragma unroll
        for (int j = 0; j < 8; ++j) acc[i][j] = 0.0f;

    int buf = 0;
#pragma unroll
    for (int ks = 0; ks < 4; ++ks) {
        if (ks < 3) {
            // prefetch next W slice into other buffer (safe: prior sync closed it)
#pragma unroll
            for (int v = 0; v < 4; ++v) {
                int idx = v * 256 + tid;
                CP_ASYNC16(sW_u + (uint32_t)((buf ^ 1) * 4096 + idx * 4) * 4u,
                           W + (ks + 1) * 4096 + idx * 4);
            }
            CP_COMMIT();
            CP_WAIT(1);     // everything except the just-issued prefetch
        } else {
            CP_WAIT(0);
        }
        __syncthreads();

        const float* sWb = sW + buf * 4096;
#pragma unroll 2
        for (int kb = 0; kb < 32; kb += 4) {
            float4 w0a = *(const float4*)&sWb[(kb + 0) * 128 + tx * 8];
            float4 w0b = *(const float4*)&sWb[(kb + 0) * 128 + tx * 8 + 4];
            float4 w1a = *(const float4*)&sWb[(kb + 1) * 128 + tx * 8];
            float4 w1b = *(const float4*)&sWb[(kb + 1) * 128 + tx * 8 + 4];
            float4 w2a = *(const float4*)&sWb[(kb + 2) * 128 + tx * 8];
            float4 w2b = *(const float4*)&sWb[(kb + 2) * 128 + tx * 8 + 4];
            float4 w3a = *(const float4*)&sWb[(kb + 3) * 128 + tx * 8];
            float4 w3b = *(const float4*)&sWb[(kb + 3) * 128 + tx * 8 + 4];
#pragma unroll
            for (int i = 0; i < 8; ++i) {
                float4 a = *(const float4*)&sA[(ty * 8 + i) * 128 + ks * 32 + kb];
                FMA8(a.x, w0a, w0b)
                FMA8(a.y, w1a, w1b)
                FMA8(a.z, w2a, w2b)
                FMA8(a.w, w3a, w3b)
            }
        }
        __syncthreads();    // close this buffer before next iter's prefetch overwrites it
        buf ^= 1;
    }

    // ---- epilogue: optional row-scale (mean), residual+bias+relu, store ----
#pragma unroll
    for (int i = 0; i < 8; ++i) {
        int grow = row0 + ty * 8 + i;
        if (grow >= n) continue;
        float sc = 1.0f;
        if (MEAN) sc = 1.0f / fmaxf(cnt[grow], 1.0f);
        float4 o0, o1;
        o0.x = acc[i][0] * sc; o0.y = acc[i][1] * sc;
        o0.z = acc[i][2] * sc; o0.w = acc[i][3] * sc;
        o1.x = acc[i][4] * sc; o1.y = acc[i][5] * sc;
        o1.z = acc[i][6] * sc; o1.w = acc[i][7] * sc;
        if (EPI) {
            const float4* rr = (const float4*)(resid + (size_t)grow * D);
            float4 r0 = rr[tx * 2], r1 = rr[tx * 2 + 1];
            float4 b0 = ((const float4*)bias)[tx * 2];
            float4 b1 = ((const float4*)bias)[tx * 2 + 1];
            o0.x = fmaxf(o0.x + r0.x + b0.x, 0.0f);
            o0.y = fmaxf(o0.y + r0.y + b0.y, 0.0f);
            o0.z = fmaxf(o0.z + r0.z + b0.z, 0.0f);
            o0.w = fmaxf(o0.w + r0.w + b0.w, 0.0f);
            o1.x = fmaxf(o1.x + r1.x + b1.x, 0.0f);
            o1.y = fmaxf(o1.y + r1.y + b1.y, 0.0f);
            o1.z = fmaxf(o1.z + r1.z + b1.z, 0.0f);
            o1.w = fmaxf(o1.w + r1.w + b1.w, 0.0f);
        }
        float4* po = (float4*)(out + (size_t)grow * D);
        po[tx * 2] = o0;
        po[tx * 2 + 1] = o1;
    }
}

// ---------------- launch ----------------
extern "C" void kernel_launch(void* const* d_in, const int* in_sizes, int n_in,
                              void* d_out, int out_size) {
    const float* emb = (const float*)d_in[0];
    const float* Wd  = (const float*)d_in[1];
    const float* bd  = (const float*)d_in[2];
    const float* Wg  = (const float*)d_in[3];
    const float* bg  = (const float*)d_in[4];
    const float* Wu  = (const float*)d_in[5];
    const float* bu  = (const float*)d_in[6];
    const int* d2u = (const int*)d_in[7];
    const int* sl  = (const int*)d_in[8];
    const int* u2d = (const int*)d_in[9];
    int nE1 = in_sizes[7] / 2;   // 100000
    int nE2 = in_sizes[8] / 2;   // 600000
    int nE3 = in_sizes[9] / 2;   // 100000
    float* out = (float*)d_out;

    float *A, *H, *X, *C;
    cudaGetSymbolAddress((void**)&A, g_A);
    cudaGetSymbolAddress((void**)&H, g_H);
    cudaGetSymbolAddress((void**)&X, g_X);
    cudaGetSymbolAddress((void**)&C, g_cnt);

    const size_t featBytes = (size_t)NN * D * sizeof(float);
    const int smemBytes = (16384 + 2 * 4096) * sizeof(float);   // 96 KB
    cudaFuncSetAttribute(gemm_kernel<true, true>,
                         cudaFuncAttributeMaxDynamicSharedMemorySize, smemBytes);
    cudaFuncSetAttribute(gemm_kernel<false, false>,
                         cudaFuncAttributeMaxDynamicSharedMemorySize, smemBytes);

    const int gemmGrid = (NN + 127) / 128;   // 782

    // ---- stage 1: down2up mean aggregate + transform + residual relu ----
    cudaMemsetAsync(A, 0, featBytes, 0);
    cudaMemsetAsync(C, 0, NN * sizeof(float), 0);
    scatter_accum_kernel<<<(nE1 + 7) / 8, 256>>>(emb, d2u, d2u + nE1, A, C, nE1);
    gemm_kernel<true, true><<<gemmGrid, 256, smemBytes>>>(A, C, Wd, bd, emb, X, NN);

    // ---- stage 2: GCN ----
    cudaMemsetAsync(C, 0, NN * sizeof(float), 0);
    degree_kernel<<<(nE2 + 255) / 256, 256>>>(sl + nE2, C, nE2);
    gemm_kernel<false, false><<<gemmGrid, 256, smemBytes>>>(X, nullptr, Wg, nullptr,
                                                            nullptr, H, NN);
    cudaMemsetAsync(A, 0, featBytes, 0);
    gcn_scatter_kernel<<<(nE2 + 7) / 8, 256>>>(H, sl, sl + nE2, C, A, nE2);
    gcn_finish_kernel<<<(NN * (D / 4) + 255) / 256, 256>>>(A, H, C, bg, X);

    // ---- stage 3: up2down mean aggregate + transform + residual relu ----
    cudaMemsetAsync(H, 0, featBytes, 0);
    cudaMemsetAsync(C, 0, NN * sizeof(float), 0);
    scatter_accum_kernel<<<(nE3 + 7) / 8, 256>>>(X, u2d, u2d + nE3, H, C, nE3);
    gemm_kernel<true, true><<<gemmGrid, 256, smemBytes>>>(H, C, Wu, bu, X, out, NN);
}

// round 13
// speedup vs baseline: 1.3935x; 1.2950x over previous
#include <cuda_runtime.h>
#include <cstdint>

#define NN 100000
#define D 128

// ---------------- scratch (no allocations allowed) ----------------
__device__ float g_A[(size_t)NN * D];   // agg / gcn-accumulator / reused
__device__ float g_H[(size_t)NN * D];   // h = x @ W_gcn / agg2
__device__ float g_X[(size_t)NN * D];   // x after down-stage / x2 after gcn
__device__ float g_cnt[NN];             // counts / degrees

// ---------------- scatter-mean accumulate: warp per edge, vector atomics ----------------
__global__ void scatter_accum_kernel(const float* __restrict__ feat,
                                     const int* __restrict__ src,
                                     const int* __restrict__ dst,
                                     float* __restrict__ agg,
                                     float* __restrict__ cnt,
                                     int nE) {
    int gtid = blockIdx.x * blockDim.x + threadIdx.x;
    int e = gtid >> 5;
    int lane = gtid & 31;
    if (e >= nE) return;
    int s = src[e];
    int d = dst[e];
    float4 v = ((const float4*)(feat + (size_t)s * D))[lane];
    atomicAdd((float4*)(agg + (size_t)d * D + lane * 4), v);
    if (lane == 0) atomicAdd(cnt + d, 1.0f);
}

// ---------------- in-degree counting (thread per edge) ----------------
__global__ void degree_kernel(const int* __restrict__ dst,
                              float* __restrict__ cnt, int nE) {
    int e = blockIdx.x * blockDim.x + threadIdx.x;
    if (e < nE) atomicAdd(cnt + dst[e], 1.0f);
}

// ---------------- GCN normalized scatter: warp per edge, vector atomics ----------------
__global__ void gcn_scatter_kernel(const float* __restrict__ h,
                                   const int* __restrict__ src,
                                   const int* __restrict__ dst,
                                   const float* __restrict__ cnt,
                                   float* __restrict__ acc,
                                   int nE) {
    int gtid = blockIdx.x * blockDim.x + threadIdx.x;
    int e = gtid >> 5;
    int lane = gtid & 31;
    if (e >= nE) return;
    int s = src[e];
    int d = dst[e];
    float norm = rsqrtf((cnt[s] + 1.0f) * (cnt[d] + 1.0f));
    float4 v = ((const float4*)(h + (size_t)s * D))[lane];
    float4 w;
    w.x = v.x * norm; w.y = v.y * norm; w.z = v.z * norm; w.w = v.w * norm;
    atomicAdd((float4*)(acc + (size_t)d * D + lane * 4), w);
}

// ---------------- GCN epilogue: x2 = acc + h/deg + b ----------------
__global__ void gcn_finish_kernel(const float* __restrict__ acc,
                                  const float* __restrict__ h,
                                  const float* __restrict__ cnt,
                                  const float* __restrict__ bias,
                                  float* __restrict__ out) {
    int i = blockIdx.x * blockDim.x + threadIdx.x;   // float4 index
    if (i >= NN * (D / 4)) return;
    int row = i >> 5;
    int c4 = i & 31;
    float inv = 1.0f / (cnt[row] + 1.0f);
    float4 a = ((const float4*)acc)[i];
    float4 hh = ((const float4*)h)[i];
    float4 b = ((const float4*)bias)[c4];
    float4 o;
    o.x = a.x + hh.x * inv + b.x;
    o.y = a.y + hh.y * inv + b.y;
    o.z = a.z + hh.z * inv + b.z;
    o.w = a.w + hh.w * inv + b.w;
    ((float4*)out)[i] = o;
}

// ---------------- fused GEMM (proven R5 version): out = f(resid + (A[/cnt]) @ W + bias) ----
// BM=64, BN=128, full K=128. 256 threads: thread (tx=tid&31, ty=tid>>5)
// computes rows ty*8..ty*8+7 x cols tx*4..tx*4+3.
template <bool MEAN, bool EPI>
__global__ void __launch_bounds__(256)
gemm128_kernel(const float* __restrict__ A, const float* __restrict__ cnt,
               const float* __restrict__ W, const float* __restrict__ bias,
               const float* __restrict__ resid, float* __restrict__ out, int n) {
    extern __shared__ float smem[];
    float* sW = smem;                 // 128 x 128
    float* sA = smem + 128 * 128;     // 64 x 132 (padded)
    const int SA_STRIDE = 132;

    int tid = threadIdx.x;
    int tx = tid & 31;
    int ty = tid >> 5;
    int row0 = blockIdx.x * 64;

    // load W (16384 floats = 4096 float4, 16 per thread)
#pragma unroll
    for (int v = 0; v < 16; ++v) {
        int idx = v * 256 + tid;          // float4 index
        int k = idx >> 5;
        int c4 = idx & 31;
        *((float4*)&sW[k * 128 + c4 * 4]) = ((const float4*)W)[idx];
    }
    // load A tile (2048 float4, 8 per thread), optional mean-divide
#pragma unroll
    for (int v = 0; v < 8; ++v) {
        int idx = v * 256 + tid;
        int r = idx >> 5;
        int c4 = idx & 31;
        int grow = row0 + r;
        float4 a = make_float4(0.f, 0.f, 0.f, 0.f);
        if (grow < n) {
            a = ((const float4*)(A + (size_t)grow * D))[c4];
            if (MEAN) {
                float inv = 1.0f / fmaxf(cnt[grow], 1.0f);
                a.x *= inv; a.y *= inv; a.z *= inv; a.w *= inv;
            }
        }
        *((float4*)&sA[r * SA_STRIDE + c4 * 4]) = a;
    }
    __syncthreads();

    float acc[8][4];
#pragma unroll
    for (int i = 0; i < 8; ++i)
#pragma unroll
        for (int j = 0; j < 4; ++j) acc[i][j] = 0.0f;

#pragma unroll 4
    for (int k = 0; k < 128; k += 4) {
        float4 w0 = *(const float4*)&sW[(k + 0) * 128 + tx * 4];
        float4 w1 = *(const float4*)&sW[(k + 1) * 128 + tx * 4];
        float4 w2 = *(const float4*)&sW[(k + 2) * 128 + tx * 4];
        float4 w3 = *(const float4*)&sW[(k + 3) * 128 + tx * 4];
#pragma unroll
        for (int i = 0; i < 8; ++i) {
            float4 a = *(const float4*)&sA[(ty * 8 + i) * SA_STRIDE + k];
            acc[i][0] = fmaf(a.x, w0.x, acc[i][0]);
            acc[i][1] = fmaf(a.x, w0.y, acc[i][1]);
            acc[i][2] = fmaf(a.x, w0.z, acc[i][2]);
            acc[i][3] = fmaf(a.x, w0.w, acc[i][3]);
            acc[i][0] = fmaf(a.y, w1.x, acc[i][0]);
            acc[i][1] = fmaf(a.y, w1.y, acc[i][1]);
            acc[i][2] = fmaf(a.y, w1.z, acc[i][2]);
            acc[i][3] = fmaf(a.y, w1.w, acc[i][3]);
            acc[i][0] = fmaf(a.z, w2.x, acc[i][0]);
            acc[i][1] = fmaf(a.z, w2.y, acc[i][1]);
            acc[i][2] = fmaf(a.z, w2.z, acc[i][2]);
            acc[i][3] = fmaf(a.z, w2.w, acc[i][3]);
            acc[i][0] = fmaf(a.w, w3.x, acc[i][0]);
            acc[i][1] = fmaf(a.w, w3.y, acc[i][1]);
            acc[i][2] = fmaf(a.w, w3.z, acc[i][2]);
            acc[i][3] = fmaf(a.w, w3.w, acc[i][3]);
        }
    }

    // epilogue
#pragma unroll
    for (int i = 0; i < 8; ++i) {
        int grow = row0 + ty * 8 + i;
        if (grow >= n) continue;
        float4 o;
        o.x = acc[i][0]; o.y = acc[i][1]; o.z = acc[i][2]; o.w = acc[i][3];
        if (EPI) {
            float4 r4 = ((const float4*)(resid + (size_t)grow * D))[tx];
            float4 b4 = ((const float4*)bias)[tx];
            o.x = fmaxf(o.x + r4.x + b4.x, 0.0f);
            o.y = fmaxf(o.y + r4.y + b4.y, 0.0f);
            o.z = fmaxf(o.z + r4.z + b4.z, 0.0f);
            o.w = fmaxf(o.w + r4.w + b4.w, 0.0f);
        }
        ((float4*)(out + (size_t)grow * D))[tx] = o;
    }
}

// ---------------- launch ----------------
extern "C" void kernel_launch(void* const* d_in, const int* in_sizes, int n_in,
                              void* d_out, int out_size) {
    const float* emb = (const float*)d_in[0];
    const float* Wd  = (const float*)d_in[1];
    const float* bd  = (const float*)d_in[2];
    const float* Wg  = (const float*)d_in[3];
    const float* bg  = (const float*)d_in[4];
    const float* Wu  = (const float*)d_in[5];
    const float* bu  = (const float*)d_in[6];
    const int* d2u = (const int*)d_in[7];
    const int* sl  = (const int*)d_in[8];
    const int* u2d = (const int*)d_in[9];
    int nE1 = in_sizes[7] / 2;   // 100000
    int nE2 = in_sizes[8] / 2;   // 600000
    int nE3 = in_sizes[9] / 2;   // 100000
    float* out = (float*)d_out;

    float *A, *H, *X, *C;
    cudaGetSymbolAddress((void**)&A, g_A);
    cudaGetSymbolAddress((void**)&H, g_H);
    cudaGetSymbolAddress((void**)&X, g_X);
    cudaGetSymbolAddress((void**)&C, g_cnt);

    const size_t featBytes = (size_t)NN * D * sizeof(float);
    const size_t smemBytes = (128 * 128 + 64 * 132) * sizeof(float);  // 99328
    cudaFuncSetAttribute(gemm128_kernel<true, true>,
                         cudaFuncAttributeMaxDynamicSharedMemorySize, (int)smemBytes);
    cudaFuncSetAttribute(gemm128_kernel<false, false>,
                         cudaFuncAttributeMaxDynamicSharedMemorySize, (int)smemBytes);

    const int gemmGrid = (NN + 63) / 64;

    // ---- stage 1: down2up mean aggregate + transform + residual relu ----
    cudaMemsetAsync(A, 0, featBytes, 0);
    cudaMemsetAsync(C, 0, NN * sizeof(float), 0);
    scatter_accum_kernel<<<(nE1 + 7) / 8, 256>>>(emb, d2u, d2u + nE1, A, C, nE1);
    gemm128_kernel<true, true><<<gemmGrid, 256, smemBytes>>>(A, C, Wd, bd, emb, X, NN);

    // ---- stage 2: GCN ----
    cudaMemsetAsync(C, 0, NN * sizeof(float), 0);
    degree_kernel<<<(nE2 + 255) / 256, 256>>>(sl + nE2, C, nE2);
    gemm128_kernel<false, false><<<gemmGrid, 256, smemBytes>>>(X, nullptr, Wg, nullptr,
                                                               nullptr, H, NN);
    cudaMemsetAsync(A, 0, featBytes, 0);
    gcn_scatter_kernel<<<(nE2 + 7) / 8, 256>>>(H, sl, sl + nE2, C, A, nE2);
    gcn_finish_kernel<<<(NN * (D / 4) + 255) / 256, 256>>>(A, H, C, bg, X);

    // ---- stage 3: up2down mean aggregate + transform + residual relu ----
    cudaMemsetAsync(H, 0, featBytes, 0);
    cudaMemsetAsync(C, 0, NN * sizeof(float), 0);
    scatter_accum_kernel<<<(nE3 + 7) / 8, 256>>>(X, u2d, u2d + nE3, H, C, nE3);
    gemm128_kernel<true, true><<<gemmGrid, 256, smemBytes>>>(H, C, Wu, bu, X, out, NN);
}

// round 14
// speedup vs baseline: 1.4667x; 1.0525x over previous
#include <cuda_runtime.h>
#include <cstdint>

#define NN 100000
#define D 128

// ---------------- scratch (no allocations allowed) ----------------
__device__ float g_A[(size_t)NN * D];   // agg / gcn x2 accumulator
__device__ float g_H[(size_t)NN * D];   // h = x @ W_gcn / agg2
__device__ float g_X[(size_t)NN * D];   // x after down-stage
__device__ float g_cnt[NN];             // counts / degrees

// ---------------- scatter-mean accumulate: warp per edge, vector atomics ----------------
__global__ void scatter_accum_kernel(const float* __restrict__ feat,
                                     const int* __restrict__ src,
                                     const int* __restrict__ dst,
                                     float* __restrict__ agg,
                                     float* __restrict__ cnt,
                                     int nE) {
    int gtid = blockIdx.x * blockDim.x + threadIdx.x;
    int e = gtid >> 5;
    int lane = gtid & 31;
    if (e >= nE) return;
    int s = src[e];
    int d = dst[e];
    float4 v = ((const float4*)(feat + (size_t)s * D))[lane];
    atomicAdd((float4*)(agg + (size_t)d * D + lane * 4), v);
    if (lane == 0) atomicAdd(cnt + d, 1.0f);
}

// ---------------- in-degree counting (thread per edge) ----------------
__global__ void degree_kernel(const int* __restrict__ dst,
                              float* __restrict__ cnt, int nE) {
    int e = blockIdx.x * blockDim.x + threadIdx.x;
    if (e < nE) atomicAdd(cnt + dst[e], 1.0f);
}

// ---------------- GCN normalized scatter: warp per edge, vector atomics ----------------
// acc already holds the self-loop term h/deg + b (written by GEMM epilogue).
__global__ void gcn_scatter_kernel(const float* __restrict__ h,
                                   const int* __restrict__ src,
                                   const int* __restrict__ dst,
                                   const float* __restrict__ cnt,
                                   float* __restrict__ acc,
                                   int nE) {
    int gtid = blockIdx.x * blockDim.x + threadIdx.x;
    int e = gtid >> 5;
    int lane = gtid & 31;
    if (e >= nE) return;
    int s = src[e];
    int d = dst[e];
    float norm = rsqrtf((cnt[s] + 1.0f) * (cnt[d] + 1.0f));
    float4 v = ((const float4*)(h + (size_t)s * D))[lane];
    float4 w;
    w.x = v.x * norm; w.y = v.y * norm; w.z = v.z * norm; w.w = v.w * norm;
    atomicAdd((float4*)(acc + (size_t)d * D + lane * 4), w);
}

// ---------------- fused GEMM (proven R5 core) ----------------
// MODE 0: out = A @ W                       (unused now)
// MODE 1: out = relu(resid + (A/cnt) @ W + bias)
// MODE 2: out = h = A @ W ;  out2 = h * (1/(cnt+1)) + bias   (GCN self-loop init)
// BM=64, BN=128, full K=128. 256 threads: thread (tx=tid&31, ty=tid>>5)
// computes rows ty*8..ty*8+7 x cols tx*4..tx*4+3.
template <int MODE>
__global__ void __launch_bounds__(256)
gemm128_kernel(const float* __restrict__ A, const float* __restrict__ cnt,
               const float* __restrict__ W, const float* __restrict__ bias,
               const float* __restrict__ resid, float* __restrict__ out,
               float* __restrict__ out2, int n) {
    extern __shared__ float smem[];
    float* sW = smem;                 // 128 x 128
    float* sA = smem + 128 * 128;     // 64 x 132 (padded)
    const int SA_STRIDE = 132;

    int tid = threadIdx.x;
    int tx = tid & 31;
    int ty = tid >> 5;
    int row0 = blockIdx.x * 64;

    // load W (16384 floats = 4096 float4, 16 per thread)
#pragma unroll
    for (int v = 0; v < 16; ++v) {
        int idx = v * 256 + tid;          // float4 index
        int k = idx >> 5;
        int c4 = idx & 31;
        *((float4*)&sW[k * 128 + c4 * 4]) = ((const float4*)W)[idx];
    }
    // load A tile (2048 float4, 8 per thread), optional mean-divide
#pragma unroll
    for (int v = 0; v < 8; ++v) {
        int idx = v * 256 + tid;
        int r = idx >> 5;
        int c4 = idx & 31;
        int grow = row0 + r;
        float4 a = make_float4(0.f, 0.f, 0.f, 0.f);
        if (grow < n) {
            a = ((const float4*)(A + (size_t)grow * D))[c4];
            if (MODE == 1) {
                float inv = 1.0f / fmaxf(cnt[grow], 1.0f);
                a.x *= inv; a.y *= inv; a.z *= inv; a.w *= inv;
            }
        }
        *((float4*)&sA[r * SA_STRIDE + c4 * 4]) = a;
    }
    __syncthreads();

    float acc[8][4];
#pragma unroll
    for (int i = 0; i < 8; ++i)
#pragma unroll
        for (int j = 0; j < 4; ++j) acc[i][j] = 0.0f;

#pragma unroll 4
    for (int k = 0; k < 128; k += 4) {
        float4 w0 = *(const float4*)&sW[(k + 0) * 128 + tx * 4];
        float4 w1 = *(const float4*)&sW[(k + 1) * 128 + tx * 4];
        float4 w2 = *(const float4*)&sW[(k + 2) * 128 + tx * 4];
        float4 w3 = *(const float4*)&sW[(k + 3) * 128 + tx * 4];
#pragma unroll
        for (int i = 0; i < 8; ++i) {
            float4 a = *(const float4*)&sA[(ty * 8 + i) * SA_STRIDE + k];
            acc[i][0] = fmaf(a.x, w0.x, acc[i][0]);
            acc[i][1] = fmaf(a.x, w0.y, acc[i][1]);
            acc[i][2] = fmaf(a.x, w0.z, acc[i][2]);
            acc[i][3] = fmaf(a.x, w0.w, acc[i][3]);
            acc[i][0] = fmaf(a.y, w1.x, acc[i][0]);
            acc[i][1] = fmaf(a.y, w1.y, acc[i][1]);
            acc[i][2] = fmaf(a.y, w1.z, acc[i][2]);
            acc[i][3] = fmaf(a.y, w1.w, acc[i][3]);
            acc[i][0] = fmaf(a.z, w2.x, acc[i][0]);
            acc[i][1] = fmaf(a.z, w2.y, acc[i][1]);
            acc[i][2] = fmaf(a.z, w2.z, acc[i][2]);
            acc[i][3] = fmaf(a.z, w2.w, acc[i][3]);
            acc[i][0] = fmaf(a.w, w3.x, acc[i][0]);
            acc[i][1] = fmaf(a.w, w3.y, acc[i][1]);
            acc[i][2] = fmaf(a.w, w3.z, acc[i][2]);
            acc[i][3] = fmaf(a.w, w3.w, acc[i][3]);
        }
    }

    // epilogue
#pragma unroll
    for (int i = 0; i < 8; ++i) {
        int grow = row0 + ty * 8 + i;
        if (grow >= n) continue;
        float4 o;
        o.x = acc[i][0]; o.y = acc[i][1]; o.z = acc[i][2]; o.w = acc[i][3];
        if (MODE == 1) {
            float4 r4 = ((const float4*)(resid + (size_t)grow * D))[tx];
            float4 b4 = ((const float4*)bias)[tx];
            o.x = fmaxf(o.x + r4.x + b4.x, 0.0f);
            o.y = fmaxf(o.y + r4.y + b4.y, 0.0f);
            o.z = fmaxf(o.z + r4.z + b4.z, 0.0f);
            o.w = fmaxf(o.w + r4.w + b4.w, 0.0f);
        }
        ((float4*)(out + (size_t)grow * D))[tx] = o;
        if (MODE == 2) {
            // self-loop init: out2 = h * (1/(deg)) + bias, deg = cnt + 1
            float inv = 1.0f / (cnt[grow] + 1.0f);
            float4 b4 = ((const float4*)bias)[tx];
            float4 o2;
            o2.x = o.x * inv + b4.x;
            o2.y = o.y * inv + b4.y;
            o2.z = o.z * inv + b4.z;
            o2.w = o.w * inv + b4.w;
            ((float4*)(out2 + (size_t)grow * D))[tx] = o2;
        }
    }
}

// ---------------- launch ----------------
extern "C" void kernel_launch(void* const* d_in, const int* in_sizes, int n_in,
                              void* d_out, int out_size) {
    const float* emb = (const float*)d_in[0];
    const float* Wd  = (const float*)d_in[1];
    const float* bd  = (const float*)d_in[2];
    const float* Wg  = (const float*)d_in[3];
    const float* bg  = (const float*)d_in[4];
    const float* Wu  = (const float*)d_in[5];
    const float* bu  = (const float*)d_in[6];
    const int* d2u = (const int*)d_in[7];
    const int* sl  = (const int*)d_in[8];
    const int* u2d = (const int*)d_in[9];
    int nE1 = in_sizes[7] / 2;   // 100000
    int nE2 = in_sizes[8] / 2;   // 600000
    int nE3 = in_sizes[9] / 2;   // 100000
    float* out = (float*)d_out;

    float *A, *H, *X, *C;
    cudaGetSymbolAddress((void**)&A, g_A);
    cudaGetSymbolAddress((void**)&H, g_H);
    cudaGetSymbolAddress((void**)&X, g_X);
    cudaGetSymbolAddress((void**)&C, g_cnt);

    const size_t featBytes = (size_t)NN * D * sizeof(float);
    const size_t smemBytes = (128 * 128 + 64 * 132) * sizeof(float);  // 99328
    cudaFuncSetAttribute(gemm128_kernel<1>,
                         cudaFuncAttributeMaxDynamicSharedMemorySize, (int)smemBytes);
    cudaFuncSetAttribute(gemm128_kernel<2>,
                         cudaFuncAttributeMaxDynamicSharedMemorySize, (int)smemBytes);

    const int gemmGrid = (NN + 63) / 64;

    // ---- stage 1: down2up mean aggregate + transform + residual relu ----
    cudaMemsetAsync(A, 0, featBytes, 0);
    cudaMemsetAsync(C, 0, NN * sizeof(float), 0);
    scatter_accum_kernel<<<(nE1 + 7) / 8, 256>>>(emb, d2u, d2u + nE1, A, C, nE1);
    gemm128_kernel<1><<<gemmGrid, 256, smemBytes>>>(A, C, Wd, bd, emb, X, nullptr, NN);

    // ---- stage 2: GCN (fused self-loop epilogue; no finish kernel, no A memset) ----
    cudaMemsetAsync(C, 0, NN * sizeof(float), 0);
    degree_kernel<<<(nE2 + 255) / 256, 256>>>(sl + nE2, C, nE2);
    // H = X @ Wg ; A = H/(deg) + bg   (A becomes the x2 accumulator)
    gemm128_kernel<2><<<gemmGrid, 256, smemBytes>>>(X, C, Wg, bg, nullptr, H, A, NN);
    gcn_scatter_kernel<<<(nE2 + 7) / 8, 256>>>(H, sl, sl + nE2, C, A, nE2);
    // A now holds x2.

    // ---- stage 3: up2down mean aggregate + transform + residual relu ----
    cudaMemsetAsync(H, 0, featBytes, 0);
    cudaMemsetAsync(C, 0, NN * sizeof(float), 0);
    scatter_accum_kernel<<<(nE3 + 7) / 8, 256>>>(A, u2d, u2d + nE3, H, C, nE3);
    gemm128_kernel<1><<<gemmGrid, 256, smemBytes>>>(H, C, Wu, bu, A, out, nullptr, NN);
}

// round 15
// speedup vs baseline: 1.5494x; 1.0564x over previous
#include <cuda_runtime.h>
#include <cstdint>

#define NN 100000
#define D 128

// ---------------- scratch (no allocations allowed) ----------------
__device__ float g_A[(size_t)NN * D];   // agg / gcn x2 accumulator
__device__ float g_H[(size_t)NN * D];   // h = x @ W_gcn / agg2
__device__ float g_X[(size_t)NN * D];   // x after down-stage
__device__ float g_cnt[NN];             // counts / degrees

__device__ __forceinline__ uint32_t f2tf32(float f) {
    uint32_t u;
    asm("cvt.rna.tf32.f32 %0, %1;" : "=r"(u) : "f"(f));
    return u;
}

// ---------------- scatter-mean accumulate: warp per edge, vector atomics ----------------
__global__ void scatter_accum_kernel(const float* __restrict__ feat,
                                     const int* __restrict__ src,
                                     const int* __restrict__ dst,
                                     float* __restrict__ agg,
                                     float* __restrict__ cnt,
                                     int nE) {
    int gtid = blockIdx.x * blockDim.x + threadIdx.x;
    int e = gtid >> 5;
    int lane = gtid & 31;
    if (e >= nE) return;
    int s = src[e];
    int d = dst[e];
    float4 v = ((const float4*)(feat + (size_t)s * D))[lane];
    atomicAdd((float4*)(agg + (size_t)d * D + lane * 4), v);
    if (lane == 0) atomicAdd(cnt + d, 1.0f);
}

// ---------------- in-degree counting ----------------
__global__ void degree_kernel(const int* __restrict__ dst,
                              float* __restrict__ cnt, int nE) {
    int e = blockIdx.x * blockDim.x + threadIdx.x;
    if (e < nE) atomicAdd(cnt + dst[e], 1.0f);
}

// ---------------- GCN normalized scatter (acc pre-loaded with self-loop term) ----------
__global__ void gcn_scatter_kernel(const float* __restrict__ h,
                                   const int* __restrict__ src,
                                   const int* __restrict__ dst,
                                   const float* __restrict__ cnt,
                                   float* __restrict__ acc,
                                   int nE) {
    int gtid = blockIdx.x * blockDim.x + threadIdx.x;
    int e = gtid >> 5;
    int lane = gtid & 31;
    if (e >= nE) return;
    int s = src[e];
    int d = dst[e];
    float norm = rsqrtf((cnt[s] + 1.0f) * (cnt[d] + 1.0f));
    float4 v = ((const float4*)(h + (size_t)s * D))[lane];
    float4 w;
    w.x = v.x * norm; w.y = v.y * norm; w.z = v.z * norm; w.w = v.w * norm;
    atomicAdd((float4*)(acc + (size_t)d * D + lane * 4), w);
}

// ================= TF32 mma.sync GEMM =================
// MODE 1: out = relu(resid + (A/cnt) @ W + bias)
// MODE 2: out = h = A @ W ;  out2 = h * (1/(cnt+1)) + bias   (GCN self-loop init)
// CTA tile 128x128, K=128. 256 threads = 8 warps (2m x 4n), warp tile 64x32.
// smem: sA [128][132] u32 (tf32 bits), sW [128][136] u32. Conflict-free frag loads.
#define SAS 132
#define SWS 136

template <int MODE>
__global__ void __launch_bounds__(256)
mma_gemm_kernel(const float* __restrict__ A, const float* __restrict__ cnt,
                const float* __restrict__ W, const float* __restrict__ bias,
                const float* __restrict__ resid, float* __restrict__ out,
                float* __restrict__ out2, int n) {
    extern __shared__ uint32_t smem_u[];
    uint32_t* sA = smem_u;                  // [128][SAS]
    uint32_t* sW = smem_u + 128 * SAS;      // [128][SWS]

    int tid = threadIdx.x;
    int wid = tid >> 5;
    int lane = tid & 31;
    int row0 = blockIdx.x * 128;

    // ---- load W -> smem (tf32-converted), row-major [k][n], stride SWS ----
#pragma unroll
    for (int v = 0; v < 16; ++v) {
        int idx = v * 256 + tid;          // float4 index over 128x128
        int k = idx >> 5, c4 = idx & 31;
        float4 w = ((const float4*)W)[idx];
        uint4 t;
        t.x = f2tf32(w.x); t.y = f2tf32(w.y); t.z = f2tf32(w.z); t.w = f2tf32(w.w);
        *((uint4*)&sW[k * SWS + c4 * 4]) = t;
    }
    // ---- load A tile -> smem (tf32), stride SAS; MODE 1 scales by 1/cnt ----
#pragma unroll
    for (int v = 0; v < 16; ++v) {
        int idx = v * 256 + tid;
        int r = idx >> 5, c4 = idx & 31;
        int grow = row0 + r;
        float4 a = make_float4(0.f, 0.f, 0.f, 0.f);
        if (grow < n) {
            a = ((const float4*)(A + (size_t)grow * D))[c4];
            if (MODE == 1) {
                float inv = 1.0f / fmaxf(cnt[grow], 1.0f);
                a.x *= inv; a.y *= inv; a.z *= inv; a.w *= inv;
            }
        }
        uint4 t;
        t.x = f2tf32(a.x); t.y = f2tf32(a.y); t.z = f2tf32(a.z); t.w = f2tf32(a.w);
        *((uint4*)&sA[r * SAS + c4 * 4]) = t;
    }
    __syncthreads();

    int mbase = (wid & 1) * 64;     // warp row base within CTA tile
    int nbase = (wid >> 1) * 32;    // warp col base
    int r0 = lane >> 2;             // groupID
    int cq = lane & 3;              // threadID_in_group

    float d[4][4][4];               // [mf][nf][reg]
#pragma unroll
    for (int mf = 0; mf < 4; ++mf)
#pragma unroll
        for (int nf = 0; nf < 4; ++nf)
#pragma unroll
            for (int q = 0; q < 4; ++q) d[mf][nf][q] = 0.0f;

#pragma unroll
    for (int k0 = 0; k0 < 128; k0 += 8) {
        uint32_t a[4][4];
#pragma unroll
        for (int mf = 0; mf < 4; ++mf) {
            const uint32_t* base = &sA[(mbase + mf * 16 + r0) * SAS + k0 + cq];
            a[mf][0] = base[0];
            a[mf][1] = base[8 * SAS];
            a[mf][2] = base[4];
            a[mf][3] = base[8 * SAS + 4];
        }
        uint32_t b[4][2];
#pragma unroll
        for (int nf = 0; nf < 4; ++nf) {
            const uint32_t* base = &sW[(k0 + cq) * SWS + nbase + nf * 8 + r0];
            b[nf][0] = base[0];
            b[nf][1] = base[4 * SWS];
        }
#pragma unroll
        for (int mf = 0; mf < 4; ++mf)
#pragma unroll
            for (int nf = 0; nf < 4; ++nf) {
                asm volatile(
                    "mma.sync.aligned.m16n8k8.row.col.f32.tf32.tf32.f32 "
                    "{%0,%1,%2,%3}, {%4,%5,%6,%7}, {%8,%9}, {%0,%1,%2,%3};"
                    : "+f"(d[mf][nf][0]), "+f"(d[mf][nf][1]),
                      "+f"(d[mf][nf][2]), "+f"(d[mf][nf][3])
                    : "r"(a[mf][0]), "r"(a[mf][1]), "r"(a[mf][2]), "r"(a[mf][3]),
                      "r"(b[nf][0]), "r"(b[nf][1]));
            }
    }

    // ---- epilogue ----
    int cpair = cq * 2;
#pragma unroll
    for (int mf = 0; mf < 4; ++mf) {
#pragma unroll
        for (int half = 0; half < 2; ++half) {
            int grow = row0 + mbase + mf * 16 + r0 + half * 8;
            if (grow >= n) continue;
            float invdeg = 0.0f;
            if (MODE == 2) invdeg = 1.0f / (cnt[grow] + 1.0f);
            float* orow = out + (size_t)grow * D;
            float* o2row = (MODE == 2) ? (out2 + (size_t)grow * D) : nullptr;
            const float* rrow = (MODE == 1) ? (resid + (size_t)grow * D) : nullptr;
#pragma unroll
            for (int nf = 0; nf < 4; ++nf) {
                int col = nbase + nf * 8 + cpair;
                float v0 = d[mf][nf][half * 2 + 0];
                float v1 = d[mf][nf][half * 2 + 1];
                if (MODE == 1) {
                    float2 rr = *(const float2*)(rrow + col);
                    float2 bb = *(const float2*)(bias + col);
                    v0 = fmaxf(v0 + rr.x + bb.x, 0.0f);
                    v1 = fmaxf(v1 + rr.y + bb.y, 0.0f);
                    *(float2*)(orow + col) = make_float2(v0, v1);
                } else {
                    *(float2*)(orow + col) = make_float2(v0, v1);
                    float2 bb = *(const float2*)(bias + col);
                    float2 o2;
                    o2.x = v0 * invdeg + bb.x;
                    o2.y = v1 * invdeg + bb.y;
                    *(float2*)(o2row + col) = o2;
                }
            }
        }
    }
}

// ---------------- launch ----------------
extern "C" void kernel_launch(void* const* d_in, const int* in_sizes, int n_in,
                              void* d_out, int out_size) {
    const float* emb = (const float*)d_in[0];
    const float* Wd  = (const float*)d_in[1];
    const float* bd  = (const float*)d_in[2];
    const float* Wg  = (const float*)d_in[3];
    const float* bg  = (const float*)d_in[4];
    const float* Wu  = (const float*)d_in[5];
    const float* bu  = (const float*)d_in[6];
    const int* d2u = (const int*)d_in[7];
    const int* sl  = (const int*)d_in[8];
    const int* u2d = (const int*)d_in[9];
    int nE1 = in_sizes[7] / 2;   // 100000
    int nE2 = in_sizes[8] / 2;   // 600000
    int nE3 = in_sizes[9] / 2;   // 100000
    float* out = (float*)d_out;

    float *A, *H, *X, *C;
    cudaGetSymbolAddress((void**)&A, g_A);
    cudaGetSymbolAddress((void**)&H, g_H);
    cudaGetSymbolAddress((void**)&X, g_X);
    cudaGetSymbolAddress((void**)&C, g_cnt);

    const size_t featBytes = (size_t)NN * D * sizeof(float);
    const int smemBytes = (128 * SAS + 128 * SWS) * 4;   // 137216
    cudaFuncSetAttribute(mma_gemm_kernel<1>,
                         cudaFuncAttributeMaxDynamicSharedMemorySize, smemBytes);
    cudaFuncSetAttribute(mma_gemm_kernel<2>,
                         cudaFuncAttributeMaxDynamicSharedMemorySize, smemBytes);

    const int gemmGrid = (NN + 127) / 128;   // 782

    // ---- stage 1: down2up mean aggregate + transform + residual relu ----
    cudaMemsetAsync(A, 0, featBytes, 0);
    cudaMemsetAsync(C, 0, NN * sizeof(float), 0);
    scatter_accum_kernel<<<(nE1 + 7) / 8, 256>>>(emb, d2u, d2u + nE1, A, C, nE1);
    mma_gemm_kernel<1><<<gemmGrid, 256, smemBytes>>>(A, C, Wd, bd, emb, X, nullptr, NN);

    // ---- stage 2: GCN (fused self-loop epilogue; no finish kernel, no A memset) ----
    cudaMemsetAsync(C, 0, NN * sizeof(float), 0);
    degree_kernel<<<(nE2 + 255) / 256, 256>>>(sl + nE2, C, nE2);
    // H = X @ Wg ; A = H/deg + bg   (A becomes the x2 accumulator)
    mma_gemm_kernel<2><<<gemmGrid, 256, smemBytes>>>(X, C, Wg, bg, nullptr, H, A, NN);
    gcn_scatter_kernel<<<(nE2 + 7) / 8, 256>>>(H, sl, sl + nE2, C, A, nE2);
    // A now holds x2.

    // ---- stage 3: up2down mean aggregate + transform + residual relu ----
    cudaMemsetAsync(H, 0, featBytes, 0);
    cudaMemsetAsync(C, 0, NN * sizeof(float), 0);
    scatter_accum_kernel<<<(nE3 + 7) / 8, 256>>>(A, u2d, u2d + nE3, H, C, nE3);
    mma_gemm_kernel<1><<<gemmGrid, 256, smemBytes>>>(H, C, Wu, bu, A, out, nullptr, NN);
}

// round 16
// speedup vs baseline: 1.8909x; 1.2204x over previous
#include <cuda_runtime.h>
#include <cstdint>

#define NN 100000
#define D 128

// ---------------- scratch (no allocations allowed) ----------------
__device__ float g_A[(size_t)NN * D];   // agg / gcn x2 accumulator
__device__ float g_H[(size_t)NN * D];   // h = x @ W_gcn / agg2
__device__ float g_X[(size_t)NN * D];   // x after down-stage
__device__ float g_cnt[NN];             // counts / degrees

__device__ __forceinline__ uint32_t f2tf32(float f) {
    uint32_t u;
    asm("cvt.rna.tf32.f32 %0, %1;" : "=r"(u) : "f"(f));
    return u;
}

// ---------------- scatter-mean accumulate: warp per edge, vector atomics ----------------
__global__ void scatter_accum_kernel(const float* __restrict__ feat,
                                     const int* __restrict__ src,
                                     const int* __restrict__ dst,
                                     float* __restrict__ agg,
                                     float* __restrict__ cnt,
                                     int nE) {
    int gtid = blockIdx.x * blockDim.x + threadIdx.x;
    int e = gtid >> 5;
    int lane = gtid & 31;
    if (e >= nE) return;
    int s = src[e];
    int d = dst[e];
    float4 v = ((const float4*)(feat + (size_t)s * D))[lane];
    atomicAdd((float4*)(agg + (size_t)d * D + lane * 4), v);
    if (lane == 0) atomicAdd(cnt + d, 1.0f);
}

// ---------------- in-degree counting ----------------
__global__ void degree_kernel(const int* __restrict__ dst,
                              float* __restrict__ cnt, int nE) {
    int e = blockIdx.x * blockDim.x + threadIdx.x;
    if (e < nE) atomicAdd(cnt + dst[e], 1.0f);
}

// ---------------- GCN normalized scatter (acc pre-loaded with self-loop term) ----------
__global__ void gcn_scatter_kernel(const float* __restrict__ h,
                                   const int* __restrict__ src,
                                   const int* __restrict__ dst,
                                   const float* __restrict__ cnt,
                                   float* __restrict__ acc,
                                   int nE) {
    int gtid = blockIdx.x * blockDim.x + threadIdx.x;
    int e = gtid >> 5;
    int lane = gtid & 31;
    if (e >= nE) return;
    int s = src[e];
    int d = dst[e];
    float norm = rsqrtf((cnt[s] + 1.0f) * (cnt[d] + 1.0f));
    float4 v = ((const float4*)(h + (size_t)s * D))[lane];
    float4 w;
    w.x = v.x * norm; w.y = v.y * norm; w.z = v.z * norm; w.w = v.w * norm;
    atomicAdd((float4*)(acc + (size_t)d * D + lane * 4), w);
}

// ================= TF32 mma.sync GEMM, BM=64 for 2 CTAs/SM =================
// MODE 1: out = relu(resid + (A/cnt) @ W + bias)
// MODE 2: out = h = A @ W ;  out2 = h * (1/(cnt+1)) + bias   (GCN self-loop init)
// CTA tile 64x128, K=128. 256 threads = 8 warps (2m x 4n), warp tile 32x32.
// smem: sA [64][132] u32 (tf32 bits) + sW [128][136] u32 = 103424 B -> 2 CTAs/SM.
#define SAS 132
#define SWS 136

template <int MODE>
__global__ void __launch_bounds__(256, 2)
mma_gemm_kernel(const float* __restrict__ A, const float* __restrict__ cnt,
                const float* __restrict__ W, const float* __restrict__ bias,
                const float* __restrict__ resid, float* __restrict__ out,
                float* __restrict__ out2, int n) {
    extern __shared__ uint32_t smem_u[];
    uint32_t* sA = smem_u;                  // [64][SAS]
    uint32_t* sW = smem_u + 64 * SAS;       // [128][SWS]

    int tid = threadIdx.x;
    int wid = tid >> 5;
    int lane = tid & 31;
    int row0 = blockIdx.x * 64;

    // ---- load W -> smem (tf32-converted), row-major [k][n], stride SWS ----
#pragma unroll
    for (int v = 0; v < 16; ++v) {
        int idx = v * 256 + tid;          // float4 index over 128x128
        int k = idx >> 5, c4 = idx & 31;
        float4 w = ((const float4*)W)[idx];
        uint4 t;
        t.x = f2tf32(w.x); t.y = f2tf32(w.y); t.z = f2tf32(w.z); t.w = f2tf32(w.w);
        *((uint4*)&sW[k * SWS + c4 * 4]) = t;
    }
    // ---- load A tile (64 rows) -> smem (tf32), stride SAS; MODE 1 scales by 1/cnt ----
#pragma unroll
    for (int v = 0; v < 8; ++v) {
        int idx = v * 256 + tid;          // 2048 float4
        int r = idx >> 5, c4 = idx & 31;
        int grow = row0 + r;
        float4 a = make_float4(0.f, 0.f, 0.f, 0.f);
        if (grow < n) {
            a = ((const float4*)(A + (size_t)grow * D))[c4];
            if (MODE == 1) {
                float inv = 1.0f / fmaxf(cnt[grow], 1.0f);
                a.x *= inv; a.y *= inv; a.z *= inv; a.w *= inv;
            }
        }
        uint4 t;
        t.x = f2tf32(a.x); t.y = f2tf32(a.y); t.z = f2tf32(a.z); t.w = f2tf32(a.w);
        *((uint4*)&sA[r * SAS + c4 * 4]) = t;
    }
    __syncthreads();

    int mbase = (wid & 1) * 32;     // warp row base within CTA tile
    int nbase = (wid >> 1) * 32;    // warp col base
    int r0 = lane >> 2;             // groupID
    int cq = lane & 3;              // threadID_in_group

    float d[2][4][4];               // [mf][nf][reg]
#pragma unroll
    for (int mf = 0; mf < 2; ++mf)
#pragma unroll
        for (int nf = 0; nf < 4; ++nf)
#pragma unroll
            for (int q = 0; q < 4; ++q) d[mf][nf][q] = 0.0f;

#pragma unroll
    for (int k0 = 0; k0 < 128; k0 += 8) {
        uint32_t a[2][4];
#pragma unroll
        for (int mf = 0; mf < 2; ++mf) {
            const uint32_t* base = &sA[(mbase + mf * 16 + r0) * SAS + k0 + cq];
            a[mf][0] = base[0];
            a[mf][1] = base[8 * SAS];
            a[mf][2] = base[4];
            a[mf][3] = base[8 * SAS + 4];
        }
        uint32_t b[4][2];
#pragma unroll
        for (int nf = 0; nf < 4; ++nf) {
            const uint32_t* base = &sW[(k0 + cq) * SWS + nbase + nf * 8 + r0];
            b[nf][0] = base[0];
            b[nf][1] = base[4 * SWS];
        }
#pragma unroll
        for (int mf = 0; mf < 2; ++mf)
#pragma unroll
            for (int nf = 0; nf < 4; ++nf) {
                asm volatile(
                    "mma.sync.aligned.m16n8k8.row.col.f32.tf32.tf32.f32 "
                    "{%0,%1,%2,%3}, {%4,%5,%6,%7}, {%8,%9}, {%0,%1,%2,%3};"
                    : "+f"(d[mf][nf][0]), "+f"(d[mf][nf][1]),
                      "+f"(d[mf][nf][2]), "+f"(d[mf][nf][3])
                    : "r"(a[mf][0]), "r"(a[mf][1]), "r"(a[mf][2]), "r"(a[mf][3]),
                      "r"(b[nf][0]), "r"(b[nf][1]));
            }
    }

    // ---- epilogue ----
    int cpair = cq * 2;
#pragma unroll
    for (int mf = 0; mf < 2; ++mf) {
#pragma unroll
        for (int half = 0; half < 2; ++half) {
            int grow = row0 + mbase + mf * 16 + r0 + half * 8;
            if (grow >= n) continue;
            float invdeg = 0.0f;
            if (MODE == 2) invdeg = 1.0f / (cnt[grow] + 1.0f);
            float* orow = out + (size_t)grow * D;
            float* o2row = (MODE == 2) ? (out2 + (size_t)grow * D) : nullptr;
            const float* rrow = (MODE == 1) ? (resid + (size_t)grow * D) : nullptr;
#pragma unroll
            for (int nf = 0; nf < 4; ++nf) {
                int col = nbase + nf * 8 + cpair;
                float v0 = d[mf][nf][half * 2 + 0];
                float v1 = d[mf][nf][half * 2 + 1];
                if (MODE == 1) {
                    float2 rr = *(const float2*)(rrow + col);
                    float2 bb = *(const float2*)(bias + col);
                    v0 = fmaxf(v0 + rr.x + bb.x, 0.0f);
                    v1 = fmaxf(v1 + rr.y + bb.y, 0.0f);
                    *(float2*)(orow + col) = make_float2(v0, v1);
                } else {
                    *(float2*)(orow + col) = make_float2(v0, v1);
                    float2 bb = *(const float2*)(bias + col);
                    float2 o2;
                    o2.x = v0 * invdeg + bb.x;
                    o2.y = v1 * invdeg + bb.y;
                    *(float2*)(o2row + col) = o2;
                }
            }
        }
    }
}

// ---------------- launch ----------------
extern "C" void kernel_launch(void* const* d_in, const int* in_sizes, int n_in,
                              void* d_out, int out_size) {
    const float* emb = (const float*)d_in[0];
    const float* Wd  = (const float*)d_in[1];
    const float* bd  = (const float*)d_in[2];
    const float* Wg  = (const float*)d_in[3];
    const float* bg  = (const float*)d_in[4];
    const float* Wu  = (const float*)d_in[5];
    const float* bu  = (const float*)d_in[6];
    const int* d2u = (const int*)d_in[7];
    const int* sl  = (const int*)d_in[8];
    const int* u2d = (const int*)d_in[9];
    int nE1 = in_sizes[7] / 2;   // 100000
    int nE2 = in_sizes[8] / 2;   // 600000
    int nE3 = in_sizes[9] / 2;   // 100000
    float* out = (float*)d_out;

    float *A, *H, *X, *C;
    cudaGetSymbolAddress((void**)&A, g_A);
    cudaGetSymbolAddress((void**)&H, g_H);
    cudaGetSymbolAddress((void**)&X, g_X);
    cudaGetSymbolAddress((void**)&C, g_cnt);

    const size_t featBytes = (size_t)NN * D * sizeof(float);
    const int smemBytes = (64 * SAS + 128 * SWS) * 4;   // 103424
    cudaFuncSetAttribute(mma_gemm_kernel<1>,
                         cudaFuncAttributeMaxDynamicSharedMemorySize, smemBytes);
    cudaFuncSetAttribute(mma_gemm_kernel<2>,
                         cudaFuncAttributeMaxDynamicSharedMemorySize, smemBytes);

    const int gemmGrid = (NN + 63) / 64;   // 1563

    // ---- stage 1: down2up mean aggregate + transform + residual relu ----
    cudaMemsetAsync(A, 0, featBytes, 0);
    cudaMemsetAsync(C, 0, NN * sizeof(float), 0);
    scatter_accum_kernel<<<(nE1 + 7) / 8, 256>>>(emb, d2u, d2u + nE1, A, C, nE1);
    mma_gemm_kernel<1><<<gemmGrid, 256, smemBytes>>>(A, C, Wd, bd, emb, X, nullptr, NN);

    // ---- stage 2: GCN (fused self-loop epilogue; no finish kernel, no A memset) ----
    cudaMemsetAsync(C, 0, NN * sizeof(float), 0);
    degree_kernel<<<(nE2 + 255) / 256, 256>>>(sl + nE2, C, nE2);
    // H = X @ Wg ; A = H/deg + bg   (A becomes the x2 accumulator)
    mma_gemm_kernel<2><<<gemmGrid, 256, smemBytes>>>(X, C, Wg, bg, nullptr, H, A, NN);
    gcn_scatter_kernel<<<(nE2 + 7) / 8, 256>>>(H, sl, sl + nE2, C, A, nE2);
    // A now holds x2.

    // ---- stage 3: up2down mean aggregate + transform + residual relu ----
    cudaMemsetAsync(H, 0, featBytes, 0);
    cudaMemsetAsync(C, 0, NN * sizeof(float), 0);
    scatter_accum_kernel<<<(nE3 + 7) / 8, 256>>>(A, u2d, u2d + nE3, H, C, nE3);
    mma_gemm_kernel<1><<<gemmGrid, 256, smemBytes>>>(H, C, Wu, bu, A, out, nullptr, NN);
}